// round 4
// baseline (speedup 1.0000x reference)
#include <cuda_runtime.h>

#define HID 100          // hidden size
#define G4  400          // 4 * HID
#define TT  128          // timesteps
#define NSEQ 12288       // 4096 cells * 3
#define SEQ_PER_CTA 48
#define NCTAS (NSEQ / SEQ_PER_CTA)   // 256
#define NTHREADS 800     // 100 j-slots * 8 groups (25 warps)
#define HS_STRIDE 68     // padded h row stride (floats)

// smem layout (float offsets)
#define OFF_W    0
#define OFF_WX   (HID * G4)                   // 40000
#define OFF_BIAS (OFF_WX + HID * 16)          // 41600
#define OFF_H0   (OFF_BIAS + G4)              // 42000
#define OFF_H1   (OFF_H0 + HID * HS_STRIDE)   // 48800
#define SMEM_FLOATS (OFF_H1 + HID * HS_STRIDE) // 55600
#define SMEM_BYTES (SMEM_FLOATS * 4)           // 222400

typedef unsigned long long ull;

// Packed weights (written by pack_kernel every launch; deterministic)
__device__ float g_Wt[HID * G4];    // [k][j][gate] : W_hh[gate*100+j][k]
__device__ float g_bias4[G4];       // [j][gate]    : b_ih + b_hh
__device__ float g_Wx4[HID * 16];   // [j][f][gate] : W_ih[gate*100+j][f]

__global__ void pack_kernel(const float* __restrict__ W_ih,
                            const float* __restrict__ W_hh,
                            const float* __restrict__ b_ih,
                            const float* __restrict__ b_hh) {
    int idx = blockIdx.x * blockDim.x + threadIdx.x;
    if (idx < HID * G4) {
        int k = idx / G4;
        int rem = idx % G4;
        int j = rem >> 2;
        int q = rem & 3;
        g_Wt[idx] = W_hh[(q * HID + j) * HID + k];
    }
    if (idx < G4) {
        int j = idx >> 2, q = idx & 3;
        g_bias4[idx] = b_ih[q * HID + j] + b_hh[q * HID + j];
    }
    if (idx < HID * 16) {
        int j = idx >> 4;
        int f = (idx >> 2) & 3;
        int q = idx & 3;
        g_Wx4[idx] = W_ih[(q * HID + j) * 4 + f];
    }
}

__device__ __forceinline__ float fsigmoid(float v) {
    return 1.0f / (1.0f + __expf(-v));
}
__device__ __forceinline__ float ftanh(float v) {
    return 1.0f - 2.0f / (1.0f + __expf(2.0f * v));
}

// f32x2 packed helpers (sm_103a FFMA2 path)
__device__ __forceinline__ ull pk2(float a, float b) {
    ull r;
    asm("mov.b64 %0, {%1, %2};" : "=l"(r) : "f"(a), "f"(b));
    return r;
}
__device__ __forceinline__ ull dup2(float a) {
    ull r;
    asm("mov.b64 %0, {%1, %1};" : "=l"(r) : "f"(a));
    return r;
}
__device__ __forceinline__ float2 upk2(ull v) {
    float2 r;
    asm("mov.b64 {%0, %1}, %2;" : "=f"(r.x), "=f"(r.y) : "l"(v));
    return r;
}
__device__ __forceinline__ ull ffma2(ull a, ull b, ull c) {
    ull d;
    asm("fma.rn.f32x2 %0, %1, %2, %3;" : "=l"(d) : "l"(a), "l"(b), "l"(c));
    return d;
}

extern __shared__ float smem[];

__global__ void __launch_bounds__(NTHREADS, 1)
lstm_kernel(const float* __restrict__ x,   // [NSEQ][TT][4]
            float* __restrict__ out)       // [NSEQ][HID]
{
    float* Ws   = smem + OFF_W;
    float* Wxs  = smem + OFF_WX;
    float* Bs   = smem + OFF_BIAS;
    float* hb0  = smem + OFF_H0;
    float* hb1  = smem + OFF_H1;

    const int tid  = threadIdx.x;
    const int j = tid % HID;           // hidden unit
    const int g = tid / HID;           // seq group 0..7, 6 seqs each

    // Cooperative smem fills
    {
        const float4* src = (const float4*)g_Wt;
        float4* dst = (float4*)Ws;
        for (int i = tid; i < (HID * G4) / 4; i += NTHREADS) dst[i] = src[i];
    }
    for (int i = tid; i < HID * 16; i += NTHREADS) Wxs[i] = g_Wx4[i];
    for (int i = tid; i < G4; i += NTHREADS)       Bs[i]  = g_bias4[i];
    // zero the t=0 read buffer
    for (int i = tid; i < HID * HS_STRIDE; i += NTHREADS) hb0[i] = 0.0f;
    __syncthreads();

    float c[6] = {0.f, 0.f, 0.f, 0.f, 0.f, 0.f};
    float hlast[6];
    const int seq0 = blockIdx.x * SEQ_PER_CTA + g * 6;
    const float* xb = x + (size_t)seq0 * (TT * 4);

    for (int t = 0; t < TT; ++t) {
        // ---- x phase: pre[gate][s] = bias + x_t . W_ih ----
        float4 bias = *(const float4*)&Bs[j * 4];
        float4 wx0 = *(const float4*)&Wxs[j * 16 + 0];
        float4 wx1 = *(const float4*)&Wxs[j * 16 + 4];
        float4 wx2 = *(const float4*)&Wxs[j * 16 + 8];
        float4 wx3 = *(const float4*)&Wxs[j * 16 + 12];

        float pi[6], pf[6], pg[6], po[6];
#pragma unroll
        for (int s = 0; s < 6; ++s) {
            float4 xv = *(const float4*)(xb + (size_t)s * (TT * 4) + t * 4);
            pi[s] = bias.x + wx0.x * xv.x + wx1.x * xv.y + wx2.x * xv.z + wx3.x * xv.w;
            pf[s] = bias.y + wx0.y * xv.x + wx1.y * xv.y + wx2.y * xv.z + wx3.y * xv.w;
            pg[s] = bias.z + wx0.z * xv.x + wx1.z * xv.y + wx2.z * xv.z + wx3.z * xv.w;
            po[s] = bias.w + wx0.w * xv.x + wx1.w * xv.y + wx2.w * xv.z + wx3.w * xv.w;
        }

        // packed accumulators: [gate][pair] over 3 seq-pairs
        ull ai0 = pk2(pi[0], pi[1]), ai1 = pk2(pi[2], pi[3]), ai2 = pk2(pi[4], pi[5]);
        ull af0 = pk2(pf[0], pf[1]), af1 = pk2(pf[2], pf[3]), af2 = pk2(pf[4], pf[5]);
        ull ag0 = pk2(pg[0], pg[1]), ag1 = pk2(pg[2], pg[3]), ag2 = pk2(pg[4], pg[5]);
        ull ao0 = pk2(po[0], po[1]), ao1 = pk2(po[2], po[3]), ao2 = pk2(po[4], po[5]);

        const float* hr = (t & 1) ? hb1 : hb0;
        float*       hw = (t & 1) ? hb0 : hb1;

        // ---- recurrent phase: FFMA2 over k ----
        const float* wp = Ws + j * 4;
        const float* hp = hr + g * 8;
#pragma unroll 2
        for (int k = 0; k < HID; ++k) {
            float4 wv = *(const float4*)(wp + k * G4);   // (wi,wf,wg,wo) for unit j
            ull wi = dup2(wv.x), wf = dup2(wv.y), wg = dup2(wv.z), wo = dup2(wv.w);
            const float* hk = hp + k * HS_STRIDE;
            ulonglong2 hAB = *(const ulonglong2*)hk;     // (h0,h1),(h2,h3)
            ull hC = *(const ull*)(hk + 4);              // (h4,h5)
            ai0 = ffma2(wi, hAB.x, ai0); ai1 = ffma2(wi, hAB.y, ai1); ai2 = ffma2(wi, hC, ai2);
            af0 = ffma2(wf, hAB.x, af0); af1 = ffma2(wf, hAB.y, af1); af2 = ffma2(wf, hC, af2);
            ag0 = ffma2(wg, hAB.x, ag0); ag1 = ffma2(wg, hAB.y, ag1); ag2 = ffma2(wg, hC, ag2);
            ao0 = ffma2(wo, hAB.x, ao0); ao1 = ffma2(wo, hAB.y, ao1); ao2 = ffma2(wo, hC, ao2);
        }

        // ---- activations ----
        float ii[6], ff[6], gg[6], oo[6];
        {
            float2 u;
            u = upk2(ai0); ii[0]=u.x; ii[1]=u.y;
            u = upk2(ai1); ii[2]=u.x; ii[3]=u.y;
            u = upk2(ai2); ii[4]=u.x; ii[5]=u.y;
            u = upk2(af0); ff[0]=u.x; ff[1]=u.y;
            u = upk2(af1); ff[2]=u.x; ff[3]=u.y;
            u = upk2(af2); ff[4]=u.x; ff[5]=u.y;
            u = upk2(ag0); gg[0]=u.x; gg[1]=u.y;
            u = upk2(ag1); gg[2]=u.x; gg[3]=u.y;
            u = upk2(ag2); gg[4]=u.x; gg[5]=u.y;
            u = upk2(ao0); oo[0]=u.x; oo[1]=u.y;
            u = upk2(ao1); oo[2]=u.x; oo[3]=u.y;
            u = upk2(ao2); oo[4]=u.x; oo[5]=u.y;
        }
#pragma unroll
        for (int s = 0; s < 6; ++s) {
            float ig = fsigmoid(ii[s]);
            float fg = fsigmoid(ff[s]);
            float tg = ftanh(gg[s]);
            float og = fsigmoid(oo[s]);
            c[s] = fg * c[s] + ig * tg;
            hlast[s] = og * ftanh(c[s]);
        }

        // ---- publish h(t) to the write buffer ----
        float* dst = hw + j * HS_STRIDE + g * 8;
        *(float4*)dst       = make_float4(hlast[0], hlast[1], hlast[2], hlast[3]);
        *(float2*)(dst + 4) = make_float2(hlast[4], hlast[5]);
        __syncthreads();
    }

#pragma unroll
    for (int s = 0; s < 6; ++s)
        out[(size_t)(seq0 + s) * HID + j] = hlast[s];
}

extern "C" void kernel_launch(void* const* d_in, const int* in_sizes, int n_in,
                              void* d_out, int out_size) {
    const float* x    = (const float*)d_in[0];  // short_ttf [4096,3,128,4]
    const float* W_ih = (const float*)d_in[1];  // [400,4]
    const float* W_hh = (const float*)d_in[2];  // [400,100]
    const float* b_ih = (const float*)d_in[3];  // [400]
    const float* b_hh = (const float*)d_in[4];  // [400]
    float* out = (float*)d_out;                 // [4096,300] == [12288,100]

    pack_kernel<<<(HID * G4 + 255) / 256, 256>>>(W_ih, W_hh, b_ih, b_hh);

    cudaFuncSetAttribute(lstm_kernel,
                         cudaFuncAttributeMaxDynamicSharedMemorySize, SMEM_BYTES);
    lstm_kernel<<<NCTAS, NTHREADS, SMEM_BYTES>>>(x, out);
}

// round 7
// speedup vs baseline: 3.5988x; 3.5988x over previous
#include <cuda_runtime.h>
#include <cstdint>

#define HID 100
#define TT 128
#define NSEQ 12288
#define MSEQ 96
#define NCTAS (NSEQ / MSEQ)   // 128
#define NW 13
#define NTH (NW * 32)         // 416
#define KD 104                // 100 h + 4 x
#define ROWS 416              // 13 groups * 32 rows (i,f,g,o × 8 j)
#define SW 108                // W row stride (≡12 mod 32, conflict-free A frags)
#define SH 104                // hs row stride (≡8 mod 32, conflict-free B frags)

#define W_FLOATS (ROWS * SW)         // 44928
#define H_FLOATS (KD * SH)           // 10816
#define SMEM_FLOATS (W_FLOATS + H_FLOATS)
#define SMEM_BYTES (SMEM_FLOATS * 4) // 222976

__device__ float g_W[W_FLOATS];      // tf32-rounded, swizzle-packed weights
__device__ float g_bias[400];        // gate-major b_ih + b_hh

__device__ __forceinline__ uint32_t tf32r(float v){uint32_t r;asm("cvt.rna.tf32.f32 %0, %1;":"=r"(r):"f"(v));return r;}
__device__ __forceinline__ float    tf32f(float v){return __uint_as_float(tf32r(v));}
__device__ __forceinline__ float tanha(float v){float r;asm("tanh.approx.f32 %0, %1;":"=f"(r):"f"(v));return r;}
__device__ __forceinline__ float sigm(float v){return 0.5f + 0.5f*tanha(0.5f*v);}

// m16n8k8 tf32 mma, D += A*B (fp32 accum)
__device__ __forceinline__ void mma8(float* d, const uint32_t* a, uint32_t b0, uint32_t b1){
  asm volatile(
    "mma.sync.aligned.m16n8k8.row.col.f32.tf32.tf32.f32 "
    "{%0,%1,%2,%3},{%4,%5,%6,%7},{%8,%9},{%0,%1,%2,%3};"
    : "+f"(d[0]),"+f"(d[1]),"+f"(d[2]),"+f"(d[3])
    : "r"(a[0]),"r"(a[1]),"r"(a[2]),"r"(a[3]),"r"(b0),"r"(b1));
}

// Pack W: row r (group w=r/32: q=r%32 -> gate=q/8, j=8w+q%8), col k.
// k<100 -> W_hh, 100..103 -> W_ih, else 0. j>=100 -> 0. tf32-rounded.
__global__ void pack_kernel(const float* __restrict__ W_ih, const float* __restrict__ W_hh,
                            const float* __restrict__ b_ih, const float* __restrict__ b_hh){
  int idx = blockIdx.x * blockDim.x + threadIdx.x;
  if (idx < ROWS * SW){
    int row = idx / SW, k = idx % SW;
    int w = row >> 5, q = row & 31, gate = q >> 3, j = (w << 3) + (q & 7);
    float v = 0.0f;
    if (j < HID && k < KD)
      v = (k < HID) ? W_hh[(gate * HID + j) * HID + k]
                    : W_ih[(gate * HID + j) * 4 + (k - HID)];
    g_W[idx] = tf32f(v);
  }
  if (idx < 400) g_bias[idx] = b_ih[idx] + b_hh[idx];
}

extern __shared__ float sm[];

__global__ void __launch_bounds__(NTH, 1)
lstm_mma(const float* __restrict__ x, float* __restrict__ out){
  float* Wm = sm;               // [ROWS][SW]
  float* hs = sm + W_FLOATS;    // [KD][SH] : rows 0..99 = h, 100..103 = x

  const int tid = threadIdx.x;
  const int w = tid >> 5, lane = tid & 31;
  const int tg = lane >> 2, tk = lane & 3;     // fragment coords
  const int j = (w << 3) + tg;                 // this thread's hidden unit
  const int r0 = w << 5;                       // group row base
  const int seq0 = blockIdx.x * MSEQ;

  // copy W to smem
  { const float4* s = (const float4*)g_W; float4* d = (float4*)Wm;
    for (int i = tid; i < W_FLOATS / 4; i += NTH) d[i] = s[i]; }
  // zero h rows 0..99 (exactly 100*SH floats)
  for (int i = tid; i < HID * SH; i += NTH) hs[i] = 0.0f;

  // x loader mapping: 384 threads, one (seq, feature) each
  const bool xl = (tid < MSEQ * 4);
  const int xs = tid >> 2, xf = tid & 3;
  const float* xptr = x + (size_t)(seq0 + xs) * (TT * 4) + xf;
  if (xl) hs[(HID + xf) * SH + xs] = tf32f(xptr[0]);   // x_0
  __syncthreads();

  const int jj = (j < HID) ? j : 0;
  const float bi = g_bias[jj], bf = g_bias[HID + jj],
              bg = g_bias[2 * HID + jj], bo = g_bias[3 * HID + jj];

  float c[24], hsv[24];
#pragma unroll
  for (int i = 0; i < 24; ++i) c[i] = 0.0f;

  for (int t = 0; t < TT; ++t){
    float xpre;
    if (xl && t + 1 < TT) xpre = xptr[(t + 1) * 4];

#pragma unroll 1
    for (int ph = 0; ph < 2; ++ph){
      float acc[6][8];
#pragma unroll
      for (int n = 0; n < 6; ++n)
#pragma unroll
        for (int e = 0; e < 8; ++e) acc[n][e] = 0.0f;

      const int nb = ph * 48;
      for (int kk = 0; kk < 13; ++kk){
        const int kb = kk * 8;
        const float* wr = Wm + (r0 + tg) * SW + kb + tk;
        uint32_t A0[4], A1[4];
        A0[0] = __float_as_uint(wr[0]);
        A0[1] = __float_as_uint(wr[8 * SW]);
        A0[2] = __float_as_uint(wr[4]);
        A0[3] = __float_as_uint(wr[8 * SW + 4]);
        const float* wr1 = wr + 16 * SW;
        A1[0] = __float_as_uint(wr1[0]);
        A1[1] = __float_as_uint(wr1[8 * SW]);
        A1[2] = __float_as_uint(wr1[4]);
        A1[3] = __float_as_uint(wr1[8 * SW + 4]);
        const float* hb = hs + (kb + tk) * SH + nb + tg;
#pragma unroll
        for (int n = 0; n < 6; ++n){
          uint32_t B0 = __float_as_uint(hb[n * 8]);
          uint32_t B1 = __float_as_uint(hb[n * 8 + 4 * SH]);
          mma8(acc[n],     A0, B0, B1);   // rows: i (c0/c1), f (c2/c3)
          mma8(acc[n] + 4, A1, B0, B1);   // rows: g (c0/c1), o (c2/c3)
        }
      }
      // epilogue: thread owns gates (i,f,g,o) of unit j for 12 seq cols
#pragma unroll
      for (int n = 0; n < 6; ++n)
#pragma unroll
        for (int e = 0; e < 2; ++e){
          const int ci = ph * 12 + n * 2 + e;
          float ig = sigm(acc[n][0 + e] + bi);
          float fg = sigm(acc[n][2 + e] + bf);
          float gg = tanha(acc[n][4 + e] + bg);
          float og = sigm(acc[n][6 + e] + bo);
          c[ci] = fg * c[ci] + ig * gg;
          hsv[ci] = og * tanha(c[ci]);
        }
    }
    __syncthreads();   // all reads of hs(t) complete

    if (t + 1 < TT){
      if (j < HID){
        float* hd = hs + j * SH;
#pragma unroll
        for (int ph = 0; ph < 2; ++ph)
#pragma unroll
          for (int n = 0; n < 6; ++n){
            const int ci = ph * 12 + n * 2;
            const int col = ph * 48 + n * 8 + 2 * tk;
            *(float2*)(hd + col) = make_float2(tf32f(hsv[ci]), tf32f(hsv[ci + 1]));
          }
      }
      if (xl) hs[(HID + xf) * SH + xs] = tf32f(xpre);
    } else if (j < HID){
#pragma unroll
      for (int ph = 0; ph < 2; ++ph)
#pragma unroll
        for (int n = 0; n < 6; ++n)
#pragma unroll
          for (int e = 0; e < 2; ++e){
            const int col = ph * 48 + n * 8 + 2 * tk + e;
            out[(size_t)(seq0 + col) * HID + j] = hsv[ph * 12 + n * 2 + e];
          }
    }
    __syncthreads();   // hs(t+1) visible
  }
}

extern "C" void kernel_launch(void* const* d_in, const int* in_sizes, int n_in,
                              void* d_out, int out_size){
  const float* x    = (const float*)d_in[0];
  const float* W_ih = (const float*)d_in[1];
  const float* W_hh = (const float*)d_in[2];
  const float* b_ih = (const float*)d_in[3];
  const float* b_hh = (const float*)d_in[4];
  float* out = (float*)d_out;

  pack_kernel<<<(ROWS * SW + 255) / 256, 256>>>(W_ih, W_hh, b_ih, b_hh);
  cudaFuncSetAttribute(lstm_mma, cudaFuncAttributeMaxDynamicSharedMemorySize, SMEM_BYTES);
  lstm_mma<<<NCTAS, NTH, SMEM_BYTES>>>(x, out);
}

// round 8
// speedup vs baseline: 5.9297x; 1.6477x over previous
#include <cuda_runtime.h>
#include <cuda_fp16.h>
#include <cstdint>

#define HID 100
#define TT 128
#define NSEQ 12288
#define MSEQ 96
#define NCTAS (NSEQ / MSEQ)   // 128
#define NW 13
#define NTH (NW * 32)         // 416
#define KD 112                // 100 h + 4 x + 8 zero pad (7 k16 steps)
#define KK 7
#define ROWS 416              // 13 groups * 32 rows (i,f,g,o × 8 j)
#define SA 120                // W row stride in halves (word stride 60: conflict-free)
#define SB 136                // hs col stride in halves (word stride 68: conflict-free)

#define W_HALFS (ROWS * SA)           // 49920
#define H_HALFS (MSEQ * SB)           // 13056 per buffer
// smem byte offsets
#define SM_W    0
#define SM_H0   (W_HALFS * 2)                 // 99840
#define SM_H1   (SM_H0 + H_HALFS * 2)         // 125952
#define SM_BIAS (SM_H1 + H_HALFS * 2)         // 152064
#define SMEM_BYTES (SM_BIAS + 400 * 4)        // 153664

__device__ __half g_W[W_HALFS];
__device__ float  g_bias[400];

__device__ __forceinline__ float tanha(float v){float r;asm("tanh.approx.f32 %0, %1;":"=f"(r):"f"(v));return r;}
__device__ __forceinline__ float sigm(float v){return 0.5f + 0.5f*tanha(0.5f*v);}

// m16n8k16 fp16 mma, fp32 accum, D += A*B
__device__ __forceinline__ void mma16(float* d, const uint32_t* a, uint32_t b0, uint32_t b1){
  asm volatile(
    "mma.sync.aligned.m16n8k16.row.col.f32.f16.f16.f32 "
    "{%0,%1,%2,%3},{%4,%5,%6,%7},{%8,%9},{%0,%1,%2,%3};"
    : "+f"(d[0]),"+f"(d[1]),"+f"(d[2]),"+f"(d[3])
    : "r"(a[0]),"r"(a[1]),"r"(a[2]),"r"(a[3]),"r"(b0),"r"(b1));
}

// Pack W rows: row r -> group w=r/32, q=r%32, gate=q/8, j=8w+q%8.
// cols: k<100 -> W_hh, 100..103 -> W_ih, 104..111 -> 0. j>=100 -> 0.
__global__ void pack_kernel(const float* __restrict__ W_ih, const float* __restrict__ W_hh,
                            const float* __restrict__ b_ih, const float* __restrict__ b_hh){
  int idx = blockIdx.x * blockDim.x + threadIdx.x;
  if (idx < W_HALFS){
    int row = idx / SA, k = idx % SA;
    int w = row >> 5, q = row & 31, gate = q >> 3, j = (w << 3) + (q & 7);
    float v = 0.0f;
    if (j < HID && k < KD){
      if (k < HID)          v = W_hh[(gate * HID + j) * HID + k];
      else if (k < HID + 4) v = W_ih[(gate * HID + j) * 4 + (k - HID)];
    }
    g_W[idx] = __float2half_rn(v);
  }
  if (idx < 400) g_bias[idx] = b_ih[idx] + b_hh[idx];
}

extern __shared__ char smc[];

__global__ void __launch_bounds__(NTH, 1)
lstm_mma(const float* __restrict__ x, float* __restrict__ out){
  __half* Wm  = (__half*)(smc + SM_W);
  __half* hs0 = (__half*)(smc + SM_H0);
  __half* hs1 = (__half*)(smc + SM_H1);
  float*  bsm = (float*)(smc + SM_BIAS);

  const int tid = threadIdx.x;
  const int w = tid >> 5, lane = tid & 31;
  const int tg = lane >> 2, tk = lane & 3;
  const int j = (w << 3) + tg;           // this thread's hidden unit (i,f,g,o owner)
  const int r0 = w << 5;
  const int seq0 = blockIdx.x * MSEQ;

  // fill smem: W, bias, zero both hs buffers
  { const float4* s = (const float4*)g_W; float4* d = (float4*)Wm;
    for (int i = tid; i < (W_HALFS * 2) / 16; i += NTH) d[i] = s[i]; }
  for (int i = tid; i < 400; i += NTH) bsm[i] = g_bias[i];
  { float4* d0 = (float4*)hs0; float4* d1 = (float4*)hs1;
    for (int i = tid; i < (H_HALFS * 2) / 16; i += NTH){ d0[i] = make_float4(0,0,0,0); d1[i] = make_float4(0,0,0,0);} }

  // x loader: 384 threads own one (seq, feature)
  const bool xl = (tid < MSEQ * 4);
  const int xs = tid >> 2, xf = tid & 3;
  const float* xptr = x + (size_t)(seq0 + xs) * (TT * 4) + xf;
  if (xl) hs0[xs * SB + HID + xf] = __float2half_rn(xptr[0]);
  __syncthreads();

  const int jj = (j < HID) ? j : 0;
  const float bi = bsm[jj], bf = bsm[HID + jj], bg = bsm[2 * HID + jj], bo = bsm[3 * HID + jj];

  float c[24];
#pragma unroll
  for (int i = 0; i < 24; ++i) c[i] = 0.0f;

  const __half* wr = Wm + (r0 + tg) * SA + 2 * tk;   // A fragment base (strip0)

  for (int t = 0; t < TT; ++t){
    const __half* hsR = (t & 1) ? hs1 : hs0;
    __half*       hsN = (t & 1) ? hs0 : hs1;
    const bool last = (t == TT - 1);
    float xpre;
    if (xl && !last) xpre = xptr[(t + 1) * 4];

#pragma unroll 1
    for (int ph = 0; ph < 2; ++ph){
      float acc[6][8];
#pragma unroll
      for (int n = 0; n < 6; ++n)
#pragma unroll
        for (int e = 0; e < 8; ++e) acc[n][e] = 0.0f;

#pragma unroll 1
      for (int kk = 0; kk < KK; ++kk){
        const int kb = kk * 16;
        uint32_t A0[4], A1[4];
        A0[0] = *(const uint32_t*)&wr[kb];
        A0[1] = *(const uint32_t*)&wr[kb + 8 * SA];
        A0[2] = *(const uint32_t*)&wr[kb + 8];
        A0[3] = *(const uint32_t*)&wr[kb + 8 * SA + 8];
        A1[0] = *(const uint32_t*)&wr[kb + 16 * SA];
        A1[1] = *(const uint32_t*)&wr[kb + 24 * SA];
        A1[2] = *(const uint32_t*)&wr[kb + 16 * SA + 8];
        A1[3] = *(const uint32_t*)&wr[kb + 24 * SA + 8];
        const __half* hb = hsR + (ph * 48 + tg) * SB + 2 * tk + kb;
#pragma unroll
        for (int n = 0; n < 6; ++n){
          uint32_t B0 = *(const uint32_t*)&hb[n * 8 * SB];
          uint32_t B1 = *(const uint32_t*)&hb[n * 8 * SB + 8];
          mma16(acc[n],     A0, B0, B1);   // rows: i (c0/c1), f (c2/c3)
          mma16(acc[n] + 4, A1, B0, B1);   // rows: g, o
        }
      }
      if (j < HID){
#pragma unroll
        for (int n = 0; n < 6; ++n)
#pragma unroll
          for (int e = 0; e < 2; ++e){
            const int ci = ph * 12 + n * 2 + e;
            const int col = ph * 48 + n * 8 + 2 * tk + e;
            float ig = sigm(acc[n][0 + e] + bi);
            float fg = sigm(acc[n][2 + e] + bf);
            float gg = tanha(acc[n][4 + e] + bg);
            float og = sigm(acc[n][6 + e] + bo);
            c[ci] = fg * c[ci] + ig * gg;
            float h = og * tanha(c[ci]);
            if (last) out[(size_t)(seq0 + col) * HID + j] = h;
            else      hsN[col * SB + j] = __float2half_rn(h);
          }
      }
    }
    if (xl && !last) hsN[xs * SB + HID + xf] = __float2half_rn(xpre);
    __syncthreads();
  }
}

extern "C" void kernel_launch(void* const* d_in, const int* in_sizes, int n_in,
                              void* d_out, int out_size){
  const float* x    = (const float*)d_in[0];
  const float* W_ih = (const float*)d_in[1];
  const float* W_hh = (const float*)d_in[2];
  const float* b_ih = (const float*)d_in[3];
  const float* b_hh = (const float*)d_in[4];
  float* out = (float*)d_out;

  pack_kernel<<<(W_HALFS + 255) / 256, 256>>>(W_ih, W_hh, b_ih, b_hh);
  cudaFuncSetAttribute(lstm_mma, cudaFuncAttributeMaxDynamicSharedMemorySize, SMEM_BYTES);
  lstm_mma<<<NCTAS, NTH, SMEM_BYTES>>>(x, out);
}